// round 5
// baseline (speedup 1.0000x reference)
#include <cuda_runtime.h>
#include <cuda_bf16.h>
#include <math.h>

#define BATCH 8
#define NPTS  2048
#define TPB   256
#define KN    16

// ---------------- scratch (no allocations allowed) ----------------
__device__ float g_cd0[BATCH * NPTS];       // min_j ||pred_i - gt_j||^2
__device__ float g_cd1[BATCH * NPTS];       // min_i ||gt_j - pred_i||^2
__device__ float g_rep[BATCH * NPTS];       // per-point repulsion partial sum (4 terms)
__device__ float g_nrm0[BATCH * NPTS * 3];  // PCA normals of pred
__device__ float g_nrm1[BATCH * NPTS * 3];  // PCA normals of gt

// =================== LAPACK single-precision ports =====================
// Faithful ports of the routines jax/XLA-CPU hits for jnp.linalg.eigh on a
// 3x3 f32 symmetric matrix: ssyevd -> ssytd2 + ssteqr(+slaev2,slartg) + sormtr.
// Sign conventions of the eigenvectors come from these routines; we replicate
// them so the sign-sensitive normal-consistency term matches the reference.

__device__ __forceinline__ float slapy2f(float x, float y) {
    float xa = fabsf(x), ya = fabsf(y);
    float w = fmaxf(xa, ya);
    float z = fminf(xa, ya);
    if (z == 0.0f) return w;
    float q = z / w;
    return w * sqrtf(1.0f + q * q);
}

// LAPACK >= 3.10 slartg
__device__ __forceinline__ void slartgf(float f, float g, float& c, float& s, float& r) {
    const float safmin = 1.17549435e-38f;
    const float safmax = 1.0f / 1.17549435e-38f;
    const float rtmin  = 1.0842021725e-19f;     // sqrt(safmin)
    const float rtmax  = 6.5219432e+18f;        // sqrt(safmax/2)
    float f1 = fabsf(f), g1 = fabsf(g);
    if (g == 0.0f) {
        c = 1.0f; s = 0.0f; r = f;
    } else if (f == 0.0f) {
        c = 0.0f; s = copysignf(1.0f, g); r = g1;
    } else {
        float d;
        if (f1 > rtmin && f1 < rtmax && g1 > rtmin && g1 < rtmax) {
            d = sqrtf(f * f + g * g);
            c = f1 / d;
            r = copysignf(d, f);
        } else {
            float u  = fminf(safmax, fmaxf(safmin, fmaxf(f1, g1)));
            float fs = f / u, gs = g / u;
            d = sqrtf(fs * fs + gs * gs);
            c = fabsf(fs) / d;
            r = copysignf(d, f) * u;
        }
        s = g / r;
    }
}

__device__ void slaev2f(float a, float b, float cc,
                        float& rt1, float& rt2, float& cs1, float& sn1) {
    float sm  = a + cc;
    float df  = a - cc;
    float adf = fabsf(df);
    float tb  = b + b;
    float ab  = fabsf(tb);
    float acmx, acmn;
    if (fabsf(a) > fabsf(cc)) { acmx = a;  acmn = cc; }
    else                      { acmx = cc; acmn = a;  }
    float rt;
    if (adf > ab)      { float q = ab / adf; rt = adf * sqrtf(1.0f + q * q); }
    else if (adf < ab) { float q = adf / ab; rt = ab  * sqrtf(1.0f + q * q); }
    else               { rt = ab * sqrtf(2.0f); }
    int sgn1;
    if (sm < 0.0f) {
        rt1 = 0.5f * (sm - rt); sgn1 = -1;
        rt2 = (acmx / rt1) * acmn - (b / rt1) * b;
    } else if (sm > 0.0f) {
        rt1 = 0.5f * (sm + rt); sgn1 = 1;
        rt2 = (acmx / rt1) * acmn - (b / rt1) * b;
    } else {
        rt1 = 0.5f * rt; rt2 = -0.5f * rt; sgn1 = 1;
    }
    int sgn2;
    float cs;
    if (df >= 0.0f) { cs = df + rt; sgn2 = 1; }
    else            { cs = df - rt; sgn2 = -1; }
    float acs = fabsf(cs);
    if (acs > ab) {
        float ct = -tb / cs;
        sn1 = 1.0f / sqrtf(1.0f + ct * ct);
        cs1 = ct * sn1;
    } else {
        if (ab == 0.0f) { cs1 = 1.0f; sn1 = 0.0f; }
        else {
            float tn = -cs / tb;
            cs1 = 1.0f / sqrtf(1.0f + tn * tn);
            sn1 = tn * cs1;
        }
    }
    if (sgn1 == sgn2) { float tn = cs1; cs1 = -sn1; sn1 = tn; }
}

// ssteqr for n=3, compz='I'.  d[1..3], e[1..2], z[1..3][1..3] (1-based).
__device__ void ssteqr3(float d[4], float e[3], float z[4][4]) {
    const float eps    = 5.9604645e-08f;   // slamch('E') single
    const float eps2   = eps * eps;
    const float safmin = 1.17549435e-38f;
    const float safmax = 1.0f / 1.17549435e-38f;
    const float ssfmax = sqrtf(safmax) / 3.0f;
    const float ssfmin = sqrtf(safmin) / eps2;
    const int n = 3;

    for (int i = 1; i <= 3; ++i)
        for (int j = 1; j <= 3; ++j)
            z[i][j] = (i == j) ? 1.0f : 0.0f;

    int nmaxit = n * 30, jtot = 0;
    int l1 = 1;
    int l = 1, m = 1, lsv = 1, lend = 1, lendsv = 1, iscale = 0;
    float anorm = 0.0f, p, g, r, c, s, f, b, rt1, rt2;
    float wc[3], ws[3];

L10:
    if (l1 > n) goto L160;
    if (l1 > 1) e[l1 - 1] = 0.0f;
    if (l1 <= n - 1) {
        for (m = l1; m <= n - 1; ++m) {
            float tst = fabsf(e[m]);
            if (tst == 0.0f) goto L30;
            if (tst <= (sqrtf(fabsf(d[m])) * sqrtf(fabsf(d[m + 1]))) * eps) {
                e[m] = 0.0f;
                goto L30;
            }
        }
    }
    m = n;
L30:
    l = l1; lsv = l; lend = m; lendsv = lend; l1 = m + 1;
    if (lend == l) goto L10;

    anorm = 0.0f;
    for (int i = l; i <= lend; ++i)     anorm = fmaxf(anorm, fabsf(d[i]));
    for (int i = l; i <= lend - 1; ++i) anorm = fmaxf(anorm, fabsf(e[i]));
    iscale = 0;
    if (anorm == 0.0f) goto L10;
    if (anorm > ssfmax) {
        iscale = 1;
        float mul = ssfmax / anorm;
        for (int i = l; i <= lend; ++i)     d[i] *= mul;
        for (int i = l; i <= lend - 1; ++i) e[i] *= mul;
    } else if (anorm < ssfmin) {
        iscale = 2;
        float mul = ssfmin / anorm;
        for (int i = l; i <= lend; ++i)     d[i] *= mul;
        for (int i = l; i <= lend - 1; ++i) e[i] *= mul;
    }

    if (fabsf(d[lend]) < fabsf(d[l])) { lend = lsv; l = lendsv; }

    if (lend > l) {
        // ---------------- QL iteration ----------------
L40:
        if (l != lend) {
            for (m = l; m <= lend - 1; ++m) {
                float tst = fabsf(e[m]); tst = tst * tst;
                if (tst <= (eps2 * fabsf(d[m])) * fabsf(d[m + 1]) + safmin) goto L60;
            }
        }
        m = lend;
L60:
        if (m < lend) e[m] = 0.0f;
        p = d[l];
        if (m == l) goto L80;
        if (m == l + 1) {
            slaev2f(d[l], e[l], d[l + 1], rt1, rt2, c, s);
            {
                float ct = c, st = s;
                if (!(ct == 1.0f && st == 0.0f)) {
                    for (int i = 1; i <= 3; ++i) {
                        float temp   = z[i][l + 1];
                        z[i][l + 1]  = ct * temp - st * z[i][l];
                        z[i][l]      = st * temp + ct * z[i][l];
                    }
                }
            }
            d[l] = rt1; d[l + 1] = rt2; e[l] = 0.0f;
            l += 2;
            if (l <= lend) goto L40;
            goto L140;
        }
        if (jtot == nmaxit) goto L140;
        ++jtot;
        g = (d[l + 1] - p) / (2.0f * e[l]);
        r = slapy2f(g, 1.0f);
        g = d[m] - p + (e[l] / (g + copysignf(r, g)));
        s = 1.0f; c = 1.0f; p = 0.0f;
        for (int i = m - 1; i >= l; --i) {
            f = s * e[i]; b = c * e[i];
            slartgf(g, f, c, s, r);
            if (i != m - 1) e[i + 1] = r;
            g = d[i + 1] - p;
            r = (d[i] - g) * s + 2.0f * c * b;
            p = s * r;
            d[i + 1] = g + p;
            g = c * r - b;
            wc[i] = c; ws[i] = -s;
        }
        {
            int mm = m - l + 1;
            for (int j = mm - 1; j >= 1; --j) {   // slasr 'R','V','B'
                float ct = wc[l + j - 1], st = ws[l + j - 1];
                if (!(ct == 1.0f && st == 0.0f)) {
                    for (int i = 1; i <= 3; ++i) {
                        float temp       = z[i][l + j];
                        z[i][l + j]      = ct * temp - st * z[i][l + j - 1];
                        z[i][l + j - 1]  = st * temp + ct * z[i][l + j - 1];
                    }
                }
            }
        }
        d[l] -= p;
        e[l] = g;
        goto L40;
L80:
        d[l] = p;
        ++l;
        if (l <= lend) goto L40;
        goto L140;
    } else {
        // ---------------- QR iteration ----------------
L90:
        if (l != lend) {
            for (m = l; m >= lend + 1; --m) {
                float tst = fabsf(e[m - 1]); tst = tst * tst;
                if (tst <= (eps2 * fabsf(d[m])) * fabsf(d[m - 1]) + safmin) goto L110;
            }
        }
        m = lend;
L110:
        if (m > lend) e[m - 1] = 0.0f;
        p = d[l];
        if (m == l) goto L130;
        if (m == l - 1) {
            slaev2f(d[l - 1], e[l - 1], d[l], rt1, rt2, c, s);
            {
                float ct = c, st = s;
                if (!(ct == 1.0f && st == 0.0f)) {
                    for (int i = 1; i <= 3; ++i) {
                        float temp  = z[i][l];
                        z[i][l]     = ct * temp - st * z[i][l - 1];
                        z[i][l - 1] = st * temp + ct * z[i][l - 1];
                    }
                }
            }
            d[l - 1] = rt1; d[l] = rt2; e[l - 1] = 0.0f;
            l -= 2;
            if (l >= lend) goto L90;
            goto L140;
        }
        if (jtot == nmaxit) goto L140;
        ++jtot;
        g = (d[l - 1] - p) / (2.0f * e[l - 1]);
        r = slapy2f(g, 1.0f);
        g = d[m] - p + (e[l - 1] / (g + copysignf(r, g)));
        s = 1.0f; c = 1.0f; p = 0.0f;
        for (int i = m; i <= l - 1; ++i) {
            f = s * e[i]; b = c * e[i];
            slartgf(g, f, c, s, r);
            if (i != m) e[i - 1] = r;
            g = d[i] - p;
            r = (d[i + 1] - g) * s + 2.0f * c * b;
            p = s * r;
            d[i] = g + p;
            g = c * r - b;
            wc[i] = c; ws[i] = s;
        }
        {
            int mm = l - m + 1;
            for (int j = 1; j <= mm - 1; ++j) {   // slasr 'R','V','F'
                float ct = wc[m + j - 1], st = ws[m + j - 1];
                if (!(ct == 1.0f && st == 0.0f)) {
                    for (int i = 1; i <= 3; ++i) {
                        float temp       = z[i][m + j];
                        z[i][m + j]      = ct * temp - st * z[i][m + j - 1];
                        z[i][m + j - 1]  = st * temp + ct * z[i][m + j - 1];
                    }
                }
            }
        }
        d[l] -= p;
        e[l - 1] = g;
        goto L90;
L130:
        d[l] = p;
        --l;
        if (l >= lend) goto L90;
        goto L140;
    }

L140:
    if (iscale == 1) {
        float mul = anorm / ssfmax;
        for (int i = lsv; i <= lendsv; ++i)     d[i] *= mul;
        for (int i = lsv; i <= lendsv - 1; ++i) e[i] *= mul;
    } else if (iscale == 2) {
        float mul = anorm / ssfmin;
        for (int i = lsv; i <= lendsv; ++i)     d[i] *= mul;
        for (int i = lsv; i <= lendsv - 1; ++i) e[i] *= mul;
    }
    if (jtot < nmaxit) goto L10;
    goto L160;

L160:
    // sort ascending, swap eigenvector columns (no sign changes)
    for (int ii = 2; ii <= n; ++ii) {
        int i = ii - 1, k = i;
        float pp = d[i];
        for (int j = ii; j <= n; ++j)
            if (d[j] < pp) { k = j; pp = d[j]; }
        if (k != i) {
            d[k] = d[i]; d[i] = pp;
            for (int rr = 1; rr <= 3; ++rr) {
                float t = z[rr][i]; z[rr][i] = z[rr][k]; z[rr][k] = t;
            }
        }
    }
}

// ssyevd('V','L') for 3x3: ssytd2 + ssteqr + sormtr; return eigvec of smallest ev.
// cov = {a00, a10, a20, a11, a21, a22} (lower triangle)
__device__ void eigvec_smallest3(const float cov[6], float nrm[3]) {
    float a00 = cov[0], a10 = cov[1], a20 = cov[2];
    float a11 = cov[3], a21 = cov[4], a22 = cov[5];

    // slarfg(2, alpha=a10, x=a20)
    float tau1, beta, v2 = 0.0f;
    float xnorm = fabsf(a20);
    if (xnorm == 0.0f) {
        tau1 = 0.0f; beta = a10;
    } else {
        beta = -copysignf(slapy2f(a10, xnorm), a10);
        tau1 = (beta - a10) / beta;
        v2   = a20 / (a10 - beta);
    }
    float e0 = beta;
    if (tau1 != 0.0f) {
        // ssymv / ssyr2 trailing-update on 2x2 block, v = [1, v2]
        float x0 = tau1 * (a11 + a21 * v2);
        float x1 = tau1 * (a21 + a22 * v2);
        float al = -0.5f * tau1 * (x0 + x1 * v2);
        x0 += al; x1 += al * v2;
        a11 = a11 - x0 - x0;
        a21 = a21 - v2 * x0 - x1;
        a22 = a22 - v2 * x1 - v2 * x1;
    }
    float d[4] = {0.0f, a00, a11, a22};
    float e[3] = {0.0f, e0, a21};
    float z[4][4];
    ssteqr3(d, e, z);

    // sormtr: apply H1 = I - tau*v*v' (rows 2..3) to column 1
    float z1 = z[1][1], z2 = z[2][1], z3 = z[3][1];
    if (tau1 != 0.0f) {
        float w = z2 + v2 * z3;
        z2 -= tau1 * w;
        z3 -= tau1 * w * v2;
    }
    nrm[0] = z1; nrm[1] = z2; nrm[2] = z3;
}

// ========================= main kernel ===============================

// stable ripple insert (ascending); caller guarantees cd < key[KN-1].
// strict '<' reproduces jax.lax.top_k tie-breaking (earlier index wins).
__device__ __forceinline__ void insert16(float (&key)[KN], int (&kid)[KN],
                                          float cd, int ci) {
    bool carry = true;
#pragma unroll
    for (int k = KN - 1; k > 0; --k) {
        bool mv = carry && (cd < key[k - 1]);
        float nk = mv ? key[k - 1] : cd;
        int   ni = mv ? kid[k - 1] : ci;
        if (carry) { key[k] = nk; kid[k] = ni; }
        carry = mv;
    }
    if (carry) { key[0] = cd; kid[0] = ci; }
}

__global__ void __launch_bounds__(TPB) loss_main_kernel(
    const float* __restrict__ pred, const float* __restrict__ gt) {
    const int side = blockIdx.z;                 // 0: own=pred, 1: own=gt
    const float* own = side ? gt : pred;
    const float* oth = side ? pred : gt;
    const int b = blockIdx.y;
    const int i = blockIdx.x * TPB + threadIdx.x;
    const float* P = own + (size_t)b * NPTS * 3;
    const float* Q = oth + (size_t)b * NPTS * 3;

    const float px = P[i * 3 + 0], py = P[i * 3 + 1], pz = P[i * 3 + 2];
    const float pn = px * px + py * py + pz * pz;

    __shared__ float sx[TPB], sy[TPB], sz[TPB], sn[TPB];

    float key[KN]; int kid[KN];
#pragma unroll
    for (int k = 0; k < KN; ++k) { key[k] = __int_as_float(0x7f800000); kid[k] = 0; }

    // ---- same-cloud 16-NN (self included; d2 = |x|^2 + |y|^2 - 2 x.y) ----
    for (int tile = 0; tile < NPTS; tile += TPB) {
        __syncthreads();
        {
            int j = tile + threadIdx.x;
            float qx = P[j * 3 + 0], qy = P[j * 3 + 1], qz = P[j * 3 + 2];
            sx[threadIdx.x] = qx; sy[threadIdx.x] = qy; sz[threadIdx.x] = qz;
            sn[threadIdx.x] = qx * qx + qy * qy + qz * qz;
        }
        __syncthreads();
#pragma unroll 4
        for (int t = 0; t < TPB; ++t) {
            float dot = px * sx[t] + py * sy[t] + pz * sz[t];
            float d2  = (pn + sn[t]) - 2.0f * dot;
            if (d2 < key[KN - 1]) insert16(key, kid, d2, tile + t);
        }
    }

    // ---- chamfer: min squared distance to the other cloud ----
    float cmin = __int_as_float(0x7f800000);
    for (int tile = 0; tile < NPTS; tile += TPB) {
        __syncthreads();
        {
            int j = tile + threadIdx.x;
            float qx = Q[j * 3 + 0], qy = Q[j * 3 + 1], qz = Q[j * 3 + 2];
            sx[threadIdx.x] = qx; sy[threadIdx.x] = qy; sz[threadIdx.x] = qz;
            sn[threadIdx.x] = qx * qx + qy * qy + qz * qz;
        }
        __syncthreads();
#pragma unroll 4
        for (int t = 0; t < TPB; ++t) {
            float dot = px * sx[t] + py * sy[t] + pz * sz[t];
            float d2  = (pn + sn[t]) - 2.0f * dot;
            cmin = fminf(cmin, d2);
        }
    }

    // ---- repulsion: nearest 4 excluding self (list entries 1..4) ----
    float rep = 0.0f;
#pragma unroll
    for (int k = 1; k <= 4; ++k) {
        float dd = sqrtf(fmaxf(key[k], 1e-12f));
        rep += fmaxf(0.02f - dd, 0.0f);
    }

    // ---- PCA normal over the 16 neighbors ----
    float nbx[KN], nby[KN], nbz[KN];
#pragma unroll
    for (int k = 0; k < KN; ++k) {
        int j = kid[k];
        nbx[k] = P[j * 3 + 0]; nby[k] = P[j * 3 + 1]; nbz[k] = P[j * 3 + 2];
    }
    float mx = 0.0f, my = 0.0f, mz = 0.0f;
#pragma unroll
    for (int k = 0; k < KN; ++k) { mx += nbx[k]; my += nby[k]; mz += nbz[k]; }
    mx *= (1.0f / KN); my *= (1.0f / KN); mz *= (1.0f / KN);
    float cxx = 0, cxy = 0, cxz = 0, cyy = 0, cyz = 0, czz = 0;
#pragma unroll
    for (int k = 0; k < KN; ++k) {
        float dx = nbx[k] - mx, dy = nby[k] - my, dz = nbz[k] - mz;
        cxx += dx * dx; cxy += dx * dy; cxz += dx * dz;
        cyy += dy * dy; cyz += dy * dz; czz += dz * dz;
    }
    const float invK = 1.0f / KN;
    float cov[6] = {cxx * invK, cxy * invK, cxz * invK,
                    cyy * invK, cyz * invK, czz * invK};
    float nrm[3];
    eigvec_smallest3(cov, nrm);

    int gidx = b * NPTS + i;
    if (side == 0) {
        g_cd0[gidx] = cmin;
        g_rep[gidx] = rep;
        g_nrm0[gidx * 3 + 0] = nrm[0];
        g_nrm0[gidx * 3 + 1] = nrm[1];
        g_nrm0[gidx * 3 + 2] = nrm[2];
    } else {
        g_cd1[gidx] = cmin;
        g_nrm1[gidx * 3 + 0] = nrm[0];
        g_nrm1[gidx * 3 + 1] = nrm[1];
        g_nrm1[gidx * 3 + 2] = nrm[2];
    }
}

// ---- deterministic final reduction (fixed order, no float atomics) ----
__global__ void __launch_bounds__(256) finalize_kernel(float* __restrict__ out) {
    __shared__ double sh0[256], sh1[256], sh2[256], sh3[256];
    const int tid = threadIdx.x;
    double c0 = 0.0, c1 = 0.0, rp = 0.0, dt = 0.0;
    for (int idx = tid; idx < BATCH * NPTS; idx += 256) {
        c0 += (double)g_cd0[idx];
        c1 += (double)g_cd1[idx];
        rp += (double)g_rep[idx];
        float dd = g_nrm0[idx * 3 + 0] * g_nrm1[idx * 3 + 0]
                 + g_nrm0[idx * 3 + 1] * g_nrm1[idx * 3 + 1]
                 + g_nrm0[idx * 3 + 2] * g_nrm1[idx * 3 + 2];
        dt += (double)dd;
    }
    sh0[tid] = c0; sh1[tid] = c1; sh2[tid] = rp; sh3[tid] = dt;
    __syncthreads();
    for (int off = 128; off > 0; off >>= 1) {
        if (tid < off) {
            sh0[tid] += sh0[tid + off];
            sh1[tid] += sh1[tid + off];
            sh2[tid] += sh2[tid + off];
            sh3[tid] += sh3[tid + off];
        }
        __syncthreads();
    }
    if (tid == 0) {
        const double inv = 1.0 / (double)(BATCH * NPTS);
        double cd    = (sh0[0] + sh1[0]) * inv;
        double rep   = sh2[0] / ((double)BATCH * NPTS * 4.0);
        double normc = 1.0 - sh3[0] * inv;
        out[0] = (float)(cd + 0.1 * rep + 0.01 * normc);
    }
}

extern "C" void kernel_launch(void* const* d_in, const int* in_sizes, int n_in,
                              void* d_out, int out_size) {
    const float* pred = (const float*)d_in[0];
    const float* gt   = (const float*)d_in[1];
    dim3 grid(NPTS / TPB, BATCH, 2);
    loss_main_kernel<<<grid, TPB>>>(pred, gt);
    finalize_kernel<<<1, 256>>>((float*)d_out);
}